// round 3
// baseline (speedup 1.0000x reference)
#include <cuda_runtime.h>
#include <cstdint>
#include <math.h>

// Problem constants (fixed by the dataset)
#define NB   16384   // batch
#define NN   30      // neighbors
#define ND   128     // model dim
#define NF   256     // 2*D concat features

// ---------------- packed f32x2 helpers ----------------
__device__ __forceinline__ void unpack2(unsigned long long v, float& lo, float& hi) {
    asm("mov.b64 {%0, %1}, %2;" : "=f"(lo), "=f"(hi) : "l"(v));
}
__device__ __forceinline__ void fma2(unsigned long long& d,
                                     unsigned long long a,
                                     unsigned long long b) {
    asm("fma.rn.f32x2 %0, %1, %2, %0;" : "+l"(d) : "l"(a), "l"(b));
}
// 128-bit global load as two packed f32x2
__device__ __forceinline__ void ldg128(const float* p,
                                       unsigned long long& a,
                                       unsigned long long& b) {
    asm("ld.global.nc.v2.u64 {%0, %1}, [%2];" : "=l"(a), "=l"(b) : "l"(p));
}
// 128-bit shared load as two packed f32x2
__device__ __forceinline__ void lds128(uint32_t addr,
                                       unsigned long long& a,
                                       unsigned long long& b) {
    asm("ld.shared.v2.u64 {%0, %1}, [%2];" : "=l"(a), "=l"(b) : "r"(addr));
}

__global__ void __launch_bounds__(128, 4)
hetro_gnn_kernel(const float* __restrict__ rel,      // [B, N, D]
                 const float* __restrict__ ent,      // [B, N, D]
                 const int*   __restrict__ mask,     // [B, N] bool -> int32
                 const float* __restrict__ Ww,       // [D, 2D]
                 const float* __restrict__ bw,       // [D]
                 const float* __restrict__ Wu,       // [1, D]
                 const float* __restrict__ bu,       // [1]
                 float* __restrict__ out)            // [B, D]
{
    __shared__ float sm_c[NN * NF];       // concat tile: [n][f], f<128 rel, f>=128 ent
    __shared__ float sm_red[4][NN];       // per-warp partial reductions
    __shared__ float sm_logit[NN];        // masked att logits

    const int b   = blockIdx.x;
    const int tid = threadIdx.x;          // tid == output dim d

    // ---- stage concat[n][0:256] into shared (coalesced) ----
    const float* relb = rel + (size_t)b * NN * ND;
    const float* entb = ent + (size_t)b * NN * ND;
    for (int idx = tid; idx < NN * NF; idx += 128) {
        const int n = idx >> 8;           // / 256
        const int f = idx & 255;
        const float v = (f < ND) ? relb[n * ND + f] : entb[n * ND + (f - ND)];
        sm_c[idx] = v;
    }
    __syncthreads();

    // ---- GEMM: h_pre[n][d] = sum_f W[d][f] * concat[n][f] ----
    // acc[n] is an f32x2 pair: lane0 accumulates even-f terms, lane1 odd-f terms.
    unsigned long long acc[NN];
#pragma unroll
    for (int n = 0; n < NN; ++n) acc[n] = 0ULL;

    const float* wrow = Ww + (size_t)tid * NF;
    const uint32_t cbase = (uint32_t)__cvta_generic_to_shared(sm_c);

    unsigned long long w01, w23, w01n, w23n;
    ldg128(wrow, w01, w23);               // prefetch f4 = 0
    for (int f4 = 0; f4 < NF / 4; ++f4) {
        const int f4n = (f4 < NF / 4 - 1) ? f4 + 1 : f4;
        ldg128(wrow + f4n * 4, w01n, w23n);   // prefetch next W chunk (L2-resident)
        const uint32_t ca = cbase + (uint32_t)(f4 * 16);
#pragma unroll
        for (int n = 0; n < NN; ++n) {
            unsigned long long c01, c23;
            lds128(ca + (uint32_t)(n * (NF * 4)), c01, c23);  // broadcast LDS
            fma2(acc[n], w01, c01);
            fma2(acc[n], w23, c23);
        }
        w01 = w01n; w23 = w23n;
    }

    // ---- epilogue: att logits via tanh + u-projection + block reduction ----
    const float uw  = Wu[tid];
    const float bwd = bw[tid];
#pragma unroll
    for (int n = 0; n < NN; ++n) {
        float lo, hi;
        unpack2(acc[n], lo, hi);
        const float h = tanhf(lo + hi + bwd);
        float v = uw * h;
#pragma unroll
        for (int off = 16; off > 0; off >>= 1)
            v += __shfl_down_sync(0xffffffffu, v, off);
        if ((tid & 31) == 0) sm_red[tid >> 5][n] = v;
    }
    __syncthreads();

    if (tid < NN) {
        float logit = sm_red[0][tid] + sm_red[1][tid] +
                      sm_red[2][tid] + sm_red[3][tid] + bu[0];
        if (mask[(size_t)b * NN + tid] != 0) logit = -INFINITY;
        sm_logit[tid] = logit;
    }
    __syncthreads();

    // ---- masked softmax over n (computed redundantly per thread) + output ----
    float maxv = -INFINITY;
#pragma unroll
    for (int n = 0; n < NN; ++n) maxv = fmaxf(maxv, sm_logit[n]);

    float ssum = 0.0f;
    float oacc = 0.0f;
#pragma unroll
    for (int n = 0; n < NN; ++n) {
        const float e = __expf(sm_logit[n] - maxv);
        ssum += e;
        oacc += e * sm_c[n * NF + ND + tid];   // ent[n][d] lives in upper half
    }

    const float o = (maxv == -INFINITY) ? 0.0f : tanhf(oacc / ssum);
    out[(size_t)b * ND + tid] = o;
}

extern "C" void kernel_launch(void* const* d_in, const int* in_sizes, int n_in,
                              void* d_out, int out_size) {
    const float* rel  = (const float*)d_in[0];
    const float* ent  = (const float*)d_in[1];
    const int*   mask = (const int*)d_in[2];
    const float* Ww   = (const float*)d_in[3];
    const float* bw   = (const float*)d_in[4];
    const float* Wu   = (const float*)d_in[5];
    const float* bu   = (const float*)d_in[6];
    float*       out  = (float*)d_out;

    hetro_gnn_kernel<<<NB, 128>>>(rel, ent, mask, Ww, bw, Wu, bu, out);
}

// round 5
// speedup vs baseline: 3.8555x; 3.8555x over previous
#include <cuda_runtime.h>
#include <cuda_bf16.h>
#include <cstdint>
#include <math.h>

#define NB 16384
#define NN 30
#define ND 128
#define NF 256
#define MROWS 64                         // concat rows per CTA
#define NCTA ((NB * NN) / MROWS)         // 7680

#define SW128(o) ((o) ^ (((o) >> 3) & 0x70))

// dynamic smem byte offsets
#define OFF_WHI 0          // [128 d][64 k] bf16, SW128 rows of 128B
#define OFF_WLO 16384
#define OFF_AHI 32768      // [64 m][64 k] bf16
#define OFF_ALO 40960
#define OFF_U   49152      // float[128]
#define OFF_BW  49664      // float[128]
#define OFF_RED 50176      // float[64][4]
#define SMEM_SZ 51200

__device__ __nv_bfloat16 g_Whi[ND * NF];
__device__ __nv_bfloat16 g_Wlo[ND * NF];
__device__ float g_logits[NB * NN];

// ---------------- helpers ----------------
__device__ __forceinline__ uint32_t pk2(float lo, float hi) {
    uint32_t r;  // element0 (low 16) = bf16(lo), element1 = bf16(hi)
    asm("cvt.rn.bf16x2.f32 %0, %1, %2;" : "=r"(r) : "f"(hi), "f"(lo));
    return r;
}
__device__ __forceinline__ float fast_tanh(float x) {
    float e = __expf(2.0f * x);
    return 1.0f - __fdividef(2.0f, e + 1.0f);
}
__device__ __forceinline__ void ldsm4(uint32_t a, uint32_t* r) {
    asm volatile("ldmatrix.sync.aligned.m8n8.x4.shared.b16 {%0,%1,%2,%3}, [%4];"
                 : "=r"(r[0]), "=r"(r[1]), "=r"(r[2]), "=r"(r[3]) : "r"(a));
}
__device__ __forceinline__ void ldsm2(uint32_t a, uint32_t* r) {
    asm volatile("ldmatrix.sync.aligned.m8n8.x2.shared.b16 {%0,%1}, [%2];"
                 : "=r"(r[0]), "=r"(r[1]) : "r"(a));
}
__device__ __forceinline__ void mma16816(float* c, const uint32_t* a,
                                         const uint32_t* b) {
    asm volatile(
        "mma.sync.aligned.m16n8k16.row.col.f32.bf16.bf16.f32 "
        "{%0,%1,%2,%3}, {%4,%5,%6,%7}, {%8,%9}, {%0,%1,%2,%3};"
        : "+f"(c[0]), "+f"(c[1]), "+f"(c[2]), "+f"(c[3])
        : "r"(a[0]), "r"(a[1]), "r"(a[2]), "r"(a[3]), "r"(b[0]), "r"(b[1]));
}

// ---- kernel 0: split W into bf16 hi/lo ----
__global__ void setup_w(const float* __restrict__ Ww) {
    int i = blockIdx.x * 256 + threadIdx.x;
    if (i < ND * NF) {
        float x = Ww[i];
        __nv_bfloat16 h = __float2bfloat16_rn(x);
        g_Whi[i] = h;
        g_Wlo[i] = __float2bfloat16_rn(x - __bfloat162float(h));
    }
}

// ---- kernel 1: bf16x3 split GEMM (mma.sync) -> logits ----
extern __shared__ __align__(128) char sm[];

__global__ void __launch_bounds__(256, 2)
gemm_logits(const float* __restrict__ rel, const float* __restrict__ ent,
            const float* __restrict__ bw, const float* __restrict__ Wu) {
    const int tid  = threadIdx.x;
    const int m0   = blockIdx.x * MROWS;
    const int wid  = tid >> 5, lane = tid & 31;
    const int dgrp = wid & 3;            // 32 d-cols per warp
    const int mgrp = wid >> 2;           // 32 m-rows per warp
    const int d0   = dgrp * 32;

    const uint32_t sb = (uint32_t)__cvta_generic_to_shared(sm);
    float* smu  = (float*)(sm + OFF_U);
    float* smbw = (float*)(sm + OFF_BW);
    float* red  = (float*)(sm + OFF_RED);

    if (tid < ND) { smu[tid] = Wu[tid]; smbw[tid] = bw[tid]; }

    float acc[2][4][4];
#pragma unroll
    for (int dt = 0; dt < 2; dt++)
#pragma unroll
        for (int nt = 0; nt < 4; nt++)
#pragma unroll
            for (int j = 0; j < 4; j++) acc[dt][nt][j] = 0.0f;

    // ldmatrix source addresses (per-lane), recomputed per kstep via swizzle.
    // W (A-op) x4: row = dbase + lane%16, kbyte = kstep*32 + (lane/16)*16
    // A (B-op) x2: row = mbase + lane%8,  kbyte = kstep*32 + ((lane>>3)&1)*16
    const int wrow_l = lane & 15, wkb_l = (lane >> 4) * 16;
    const int arow_l = lane & 7,  akb_l = ((lane >> 3) & 1) * 16;

    for (int q = 0; q < 4; q++) {
        // ---- stage W chunk (hi+lo) [128][64] ----
#pragma unroll
        for (int j = 0; j < 4; j++) {
            int cid = tid + j * 256;          // 1024 chunks of 16B
            int row = cid >> 3, kcb = cid & 7;
            uint32_t off = SW128((uint32_t)(row * 128 + kcb * 16));
            *(uint4*)(sm + OFF_WHI + off) =
                *(const uint4*)(g_Whi + row * NF + q * 64 + kcb * 8);
            *(uint4*)(sm + OFF_WLO + off) =
                *(const uint4*)(g_Wlo + row * NF + q * 64 + kcb * 8);
        }
        // ---- stage + split A chunk [64 rows][64 feats] ----
        const float* srcp = (q < 2) ? rel : ent;
#pragma unroll
        for (int j = 0; j < 2; j++) {
            int uid = tid + j * 256;          // 512 units of 8 floats
            int row = uid >> 3, kcb = uid & 7;
            const float* s = srcp + (size_t)(m0 + row) * ND + (q & 1) * 64 + kcb * 8;
            float4 fa = __ldg((const float4*)s);
            float4 fb = __ldg((const float4*)(s + 4));
            uint32_t ha = pk2(fa.x, fa.y), hb = pk2(fa.z, fa.w);
            uint32_t hc = pk2(fb.x, fb.y), hd = pk2(fb.z, fb.w);
            float l0 = fa.x - __uint_as_float(ha << 16);
            float l1 = fa.y - __uint_as_float(ha & 0xFFFF0000u);
            float l2 = fa.z - __uint_as_float(hb << 16);
            float l3 = fa.w - __uint_as_float(hb & 0xFFFF0000u);
            float l4 = fb.x - __uint_as_float(hc << 16);
            float l5 = fb.y - __uint_as_float(hc & 0xFFFF0000u);
            float l6 = fb.z - __uint_as_float(hd << 16);
            float l7 = fb.w - __uint_as_float(hd & 0xFFFF0000u);
            uint32_t off = SW128((uint32_t)(row * 128 + kcb * 16));
            *(uint4*)(sm + OFF_AHI + off) = make_uint4(ha, hb, hc, hd);
            *(uint4*)(sm + OFF_ALO + off) =
                make_uint4(pk2(l0, l1), pk2(l2, l3), pk2(l4, l5), pk2(l6, l7));
        }
        __syncthreads();

        // ---- compute: 4 k-steps of 16 ----
#pragma unroll
        for (int ks = 0; ks < 4; ks++) {
            uint32_t wh[2][4], wl[2][4], ah[4][2], al[4][2];
#pragma unroll
            for (int dt = 0; dt < 2; dt++) {
                uint32_t o = SW128((uint32_t)((d0 + dt * 16 + wrow_l) * 128 +
                                              ks * 32 + wkb_l));
                ldsm4(sb + OFF_WHI + o, wh[dt]);
                ldsm4(sb + OFF_WLO + o, wl[dt]);
            }
#pragma unroll
            for (int nt = 0; nt < 4; nt++) {
                uint32_t o = SW128((uint32_t)((mgrp * 32 + nt * 8 + arow_l) * 128 +
                                              ks * 32 + akb_l));
                ldsm2(sb + OFF_AHI + o, ah[nt]);
                ldsm2(sb + OFF_ALO + o, al[nt]);
            }
#pragma unroll
            for (int dt = 0; dt < 2; dt++)
#pragma unroll
                for (int nt = 0; nt < 4; nt++) {
                    mma16816(acc[dt][nt], wh[dt], ah[nt]);   // hi*hi
                    mma16816(acc[dt][nt], wl[dt], ah[nt]);   // lo_w*hi_a
                    mma16816(acc[dt][nt], wh[dt], al[nt]);   // hi_w*lo_a
                }
        }
        __syncthreads();
    }

    // ---- epilogue: logit[m] = sum_d u_d * tanh(hpre + bw_d) ----
    const int g = lane >> 2, cq = lane & 3;
#pragma unroll
    for (int nt = 0; nt < 4; nt++) {
#pragma unroll
        for (int par = 0; par < 2; par++) {
            float p = 0.0f;
#pragma unroll
            for (int dt = 0; dt < 2; dt++) {
                int dlo = d0 + dt * 16 + g, dhi = dlo + 8;
                p = fmaf(smu[dlo], fast_tanh(acc[dt][nt][par] + smbw[dlo]), p);
                p = fmaf(smu[dhi], fast_tanh(acc[dt][nt][2 + par] + smbw[dhi]), p);
            }
            p += __shfl_down_sync(0xffffffffu, p, 16);
            p += __shfl_down_sync(0xffffffffu, p, 8);
            p += __shfl_down_sync(0xffffffffu, p, 4);
            if (lane < 4)
                red[(mgrp * 32 + nt * 8 + lane * 2 + par) * 4 + dgrp] = p;
        }
    }
    __syncthreads();
    if (tid < MROWS) {
        g_logits[m0 + tid] = red[tid * 4] + red[tid * 4 + 1] +
                             red[tid * 4 + 2] + red[tid * 4 + 3];
    }
}

// ---- kernel 2: masked softmax over n + weighted ent sum + tanh ----
// b_u dropped: softmax(x + c) == softmax(x).
__global__ void __launch_bounds__(128)
softmax_out(const float* __restrict__ ent, const int* __restrict__ mask,
            float* __restrict__ out) {
    __shared__ float sl[NN];
    const int b = blockIdx.x, tid = threadIdx.x;
    if (tid < NN) {
        float lg = g_logits[b * NN + tid];
        if (mask[b * NN + tid] != 0) lg = -INFINITY;
        sl[tid] = lg;
    }
    __syncthreads();
    float mx = -INFINITY;
#pragma unroll
    for (int n = 0; n < NN; n++) mx = fmaxf(mx, sl[n]);
    float ss = 0.0f, oa = 0.0f;
    const float* eb = ent + (size_t)b * NN * ND + tid;
#pragma unroll
    for (int n = 0; n < NN; n++) {
        float e = __expf(sl[n] - mx);
        ss += e;
        oa = fmaf(e, eb[n * ND], oa);
    }
    out[(size_t)b * ND + tid] = (mx == -INFINITY) ? 0.0f : fast_tanh(oa / ss);
}

extern "C" void kernel_launch(void* const* d_in, const int* in_sizes, int n_in,
                              void* d_out, int out_size) {
    const float* rel  = (const float*)d_in[0];
    const float* ent  = (const float*)d_in[1];
    const int*   mask = (const int*)d_in[2];
    const float* Ww   = (const float*)d_in[3];
    const float* bw   = (const float*)d_in[4];
    const float* Wu   = (const float*)d_in[5];
    float*       out  = (float*)d_out;

    cudaFuncSetAttribute(gemm_logits,
                         cudaFuncAttributeMaxDynamicSharedMemorySize, SMEM_SZ);
    setup_w<<<(ND * NF + 255) / 256, 256>>>(Ww);
    gemm_logits<<<NCTA, 256, SMEM_SZ>>>(rel, ent, bw, Wu);
    softmax_out<<<NB, 128>>>(ent, mask, out);
}